// round 13
// baseline (speedup 1.0000x reference)
#include <cuda_runtime.h>
#include <math.h>

#define H 128
#define B 512
#define RANKS 3
#define POOL_BLOCKS_X 512
#define POOL_THREADS 256
#define POOL_WARPS_PER_RANK (POOL_BLOCKS_X * POOL_THREADS / 32)

// ---------------- scratch (no allocations allowed) ----------------
__device__ float g_sum [RANKS][B * H];
__device__ float g_gsum[RANKS][B * H];
__device__ float g_max [RANKS][B * H];
__device__ float g_cnt [RANKS][B];
__device__ float g_state[B][3 * H];   // seeded with bp, accumulated by proj
__device__ float g_x[B][H];           // seeded with b1f, accumulated by final

__device__ __forceinline__ void atomicMaxF(float* addr, float v) {
    if (v >= 0.f) atomicMax((int*)addr, __float_as_int(v));
    else          atomicMin((unsigned int*)addr, __float_as_uint(v));
}

// ---------------- init: reset + bias-seed every replay ----------------
__global__ void init_kernel(const float* __restrict__ bp0,
                            const float* __restrict__ bp1,
                            const float* __restrict__ bp2,
                            const float* __restrict__ b1f) {
    int i = blockIdx.x * blockDim.x + threadIdx.x;
    int stride = gridDim.x * blockDim.x;
    int tot = RANKS * B * H;
    for (int idx = i; idx < tot; idx += stride) {
        int r = idx / (B * H);
        int o = idx - r * (B * H);
        g_sum[r][o]  = 0.f;
        g_gsum[r][o] = 0.f;
        g_max[r][o]  = -INFINITY;
    }
    // g_state[seg][rank*H + j] = bp_rank[j]
    for (int idx = i; idx < B * 3 * H; idx += stride) {
        int seg = idx / (3 * H);
        int k = idx - seg * (3 * H);
        int r = k >> 7;          // k / 128
        int j = k & 127;
        float bv = (r == 0) ? bp0[j] : (r == 1) ? bp1[j] : bp2[j];
        g_state[seg][k] = bv;
    }
    for (int idx = i; idx < B * H; idx += stride) {
        g_x[idx / H][idx & 127] = b1f[idx & 127];
    }
    if (i < RANKS * B) g_cnt[i / B][i % B] = 0.f;
}

// ---------------- stage 1: fused gated multi-agg pooling (all 3 ranks) ----
__global__ void __launch_bounds__(POOL_THREADS)
pool_kernel(const float* __restrict__ h0, const float* __restrict__ h1,
            const float* __restrict__ h2,
            const int* __restrict__ bb0, const int* __restrict__ bb1,
            const int* __restrict__ bb2,
            const float* __restrict__ Wg0, const float* __restrict__ Wg1,
            const float* __restrict__ Wg2,
            const float* __restrict__ bgp0, const float* __restrict__ bgp1,
            const float* __restrict__ bgp2,
            int N0, int N1, int N2) {
    int rank = blockIdx.y;
    const float* __restrict__ h  = (rank == 0) ? h0  : (rank == 1) ? h1  : h2;
    const int*   __restrict__ b  = (rank == 0) ? bb0 : (rank == 1) ? bb1 : bb2;
    const float* __restrict__ Wg = (rank == 0) ? Wg0 : (rank == 1) ? Wg1 : Wg2;
    const float* __restrict__ bg = (rank == 0) ? bgp0 : (rank == 1) ? bgp1 : bgp2;
    int N = (rank == 0) ? N0 : (rank == 1) ? N1 : N2;

    int npw = (N + POOL_WARPS_PER_RANK - 1) / POOL_WARPS_PER_RANK;
    int gwid = (blockIdx.x * blockDim.x + threadIdx.x) >> 5;
    int lane = threadIdx.x & 31;
    int start = gwid * npw;
    if (start >= N) return;
    int end = min(N, start + npw);

    float4 wg = reinterpret_cast<const float4*>(Wg)[lane];
    float bgv = bg[0];

    float* __restrict__ sums  = g_sum[rank];
    float* __restrict__ gsums = g_gsum[rank];
    float* __restrict__ maxs  = g_max[rank];
    float* __restrict__ cnts  = g_cnt[rank];

    const float4* __restrict__ h4 = reinterpret_cast<const float4*>(h);

    int cur = b[start];
    float4 s4  = make_float4(0.f, 0.f, 0.f, 0.f);
    float4 gs4 = make_float4(0.f, 0.f, 0.f, 0.f);
    float4 m4  = make_float4(-INFINITY, -INFINITY, -INFINITY, -INFINITY);
    float  c   = 0.f;

    auto flush = [&]() {
        int base = cur * H + (lane << 2);
        atomicAdd(&sums[base + 0], s4.x);
        atomicAdd(&sums[base + 1], s4.y);
        atomicAdd(&sums[base + 2], s4.z);
        atomicAdd(&sums[base + 3], s4.w);
        atomicAdd(&gsums[base + 0], gs4.x);
        atomicAdd(&gsums[base + 1], gs4.y);
        atomicAdd(&gsums[base + 2], gs4.z);
        atomicAdd(&gsums[base + 3], gs4.w);
        atomicMaxF(&maxs[base + 0], m4.x);
        atomicMaxF(&maxs[base + 1], m4.y);
        atomicMaxF(&maxs[base + 2], m4.z);
        atomicMaxF(&maxs[base + 3], m4.w);
        if (lane == 0) atomicAdd(&cnts[cur], c);
    };

    auto acc1 = [&](const float4& v, float g) {
        s4.x += v.x;  s4.y += v.y;  s4.z += v.z;  s4.w += v.w;
        m4.x = fmaxf(m4.x, v.x);  m4.y = fmaxf(m4.y, v.y);
        m4.z = fmaxf(m4.z, v.z);  m4.w = fmaxf(m4.w, v.w);
        gs4.x += g * v.x;  gs4.y += g * v.y;
        gs4.z += g * v.z;  gs4.w += g * v.w;
        c += 1.f;
    };

    int n = start;
    while (n < end) {
        if (n + 8 <= end) {
            int same = 1;
            #pragma unroll
            for (int u = 0; u < 8; ++u) same &= (b[n + u] == cur);
            if (same) {
                float4 v[8];
                #pragma unroll
                for (int u = 0; u < 8; ++u)
                    v[u] = __ldcs(&h4[(n + u) * 32 + lane]);
                float p[8];
                #pragma unroll
                for (int u = 0; u < 8; ++u)
                    p[u] = v[u].x * wg.x + v[u].y * wg.y + v[u].z * wg.z + v[u].w * wg.w;
                #pragma unroll
                for (int o = 16; o; o >>= 1) {
                    #pragma unroll
                    for (int u = 0; u < 8; ++u)
                        p[u] += __shfl_xor_sync(0xffffffffu, p[u], o);
                }
                #pragma unroll
                for (int u = 0; u < 8; ++u) {
                    float g = 1.f / (1.f + __expf(-(p[u] + bgv)));
                    acc1(v[u], g);
                }
                n += 8;
                continue;
            }
        }
        int seg = b[n];
        float4 v = __ldcs(&h4[n * 32 + lane]);
        if (seg != cur) {
            flush();
            s4  = make_float4(0.f, 0.f, 0.f, 0.f);
            gs4 = make_float4(0.f, 0.f, 0.f, 0.f);
            m4  = make_float4(-INFINITY, -INFINITY, -INFINITY, -INFINITY);
            c   = 0.f;
            cur = seg;
        }
        float p = v.x * wg.x + v.y * wg.y + v.z * wg.z + v.w * wg.w;
        #pragma unroll
        for (int o = 16; o; o >>= 1) p += __shfl_xor_sync(0xffffffffu, p, o);
        float g = 1.f / (1.f + __expf(-(p + bgv)));
        acc1(v, g);
        ++n;
    }
    flush();
}

// ---------------- stage 2: split-K projection with atomic accumulate ------
// grid (32, 4, 3): x = 16-seg tile, y = K-quarter q (agg source), z = rank.
// 256 threads = 8 warps; warp owns 2 segments, streams the full 128-wide
// K-quarter. All warps read the SAME weight rows -> L1 dedup. Results
// atomicAdd into g_state (pre-seeded with bias).
__global__ void proj_kernel(const float* __restrict__ Wp0,
                            const float* __restrict__ Wp1,
                            const float* __restrict__ Wp2) {
    int rank = blockIdx.z;
    int q    = blockIdx.y;            // 0=sum 1=mean 2=max 3=gsum
    int seg0 = blockIdx.x * 16;
    int tid  = threadIdx.x;
    const float* Wp = (rank == 0) ? Wp0 : (rank == 1) ? Wp1 : Wp2;

    __shared__ float a[16][128];
    __shared__ float csh[16];

    if (tid < 16) csh[tid] = g_cnt[rank][seg0 + tid];
    __syncthreads();

    const float* __restrict__ src =
        (q == 3) ? g_gsum[rank] : (q == 2) ? g_max[rank] : g_sum[rank];

    for (int idx = tid; idx < 16 * 128; idx += 256) {
        int s = idx >> 7;
        int k = idx & 127;
        float v = src[(seg0 + s) * H + k];
        if (q == 1)      v *= 1.f / fmaxf(csh[s], 1.f);
        else if (q == 2) v = (csh[s] > 0.f) ? v : 0.f;
        a[s][k] = v;
    }
    __syncthreads();

    int wid  = tid >> 5;
    int lane = tid & 31;
    int sA = wid * 2, sB = sA + 1;

    const float4* W4 = reinterpret_cast<const float4*>(Wp) + q * 128 * 32 + lane;
    float4 r0 = make_float4(0.f, 0.f, 0.f, 0.f);
    float4 r1 = make_float4(0.f, 0.f, 0.f, 0.f);

    #pragma unroll 8
    for (int k = 0; k < 128; ++k) {
        float4 w = W4[k * 32];
        float a0 = a[sA][k];
        float a1 = a[sB][k];
        r0.x += a0 * w.x; r0.y += a0 * w.y; r0.z += a0 * w.z; r0.w += a0 * w.w;
        r1.x += a1 * w.x; r1.y += a1 * w.y; r1.z += a1 * w.z; r1.w += a1 * w.w;
    }

    float* d0 = &g_state[seg0 + sA][rank * H + lane * 4];
    float* d1 = &g_state[seg0 + sB][rank * H + lane * 4];
    atomicAdd(d0 + 0, r0.x); atomicAdd(d0 + 1, r0.y);
    atomicAdd(d0 + 2, r0.z); atomicAdd(d0 + 3, r0.w);
    atomicAdd(d1 + 0, r1.x); atomicAdd(d1 + 1, r1.y);
    atomicAdd(d1 + 2, r1.z); atomicAdd(d1 + 3, r1.w);
}

// ---------------- stage 3: LN + SiLU + MLP1 (split-K, atomic) -------------
// grid (64, 3): x = 8-seg tile, y = K-third t. Block stages 8 full rows,
// does LN+SiLU (redundant per third, trivial), then warp-per-seg GEMM over
// the 128-wide K-third; atomicAdd into g_x (seeded with b1f).
__global__ void final_kernel(const float* __restrict__ gamma,
                             const float* __restrict__ beta,
                             const float* __restrict__ W1) {
    int t    = blockIdx.y;
    int seg0 = blockIdx.x * 8;
    int tid  = threadIdx.x;
    int wid  = tid >> 5;
    int lane = tid & 31;

    __shared__ float a[8][384];

    for (int idx = tid; idx < 8 * 384; idx += 256) {
        int s = idx / 384;
        int k = idx - s * 384;
        a[s][k] = g_state[seg0 + s][k];
    }
    __syncthreads();

    // LN + SiLU: warp wid handles row wid; only its K-third gets written back
    {
        int s = wid;
        float ps = 0.f;
        #pragma unroll
        for (int kk = 0; kk < 12; ++kk) ps += a[s][lane + kk * 32];
        #pragma unroll
        for (int o = 16; o; o >>= 1) ps += __shfl_xor_sync(0xffffffffu, ps, o);
        float mu = ps * (1.f / 384.f);
        float pv = 0.f;
        #pragma unroll
        for (int kk = 0; kk < 12; ++kk) {
            float d = a[s][lane + kk * 32] - mu;
            pv += d * d;
        }
        #pragma unroll
        for (int o = 16; o; o >>= 1) pv += __shfl_xor_sync(0xffffffffu, pv, o);
        float rstd = rsqrtf(pv * (1.f / 384.f) + 1e-5f);
        #pragma unroll
        for (int kk = 0; kk < 4; ++kk) {
            int k = t * 128 + lane + kk * 32;
            float xn = (a[s][k] - mu) * rstd * gamma[k] + beta[k];
            a[s][k] = xn / (1.f + __expf(-xn));   // silu
        }
    }
    __syncthreads();

    const float4* W4 = reinterpret_cast<const float4*>(W1) + t * 128 * 32 + lane;
    float4 r = make_float4(0.f, 0.f, 0.f, 0.f);
    #pragma unroll 8
    for (int k = 0; k < 128; ++k) {
        float4 w = W4[k * 32];
        float av = a[wid][t * 128 + k];
        r.x += av * w.x; r.y += av * w.y; r.z += av * w.z; r.w += av * w.w;
    }

    float* dst = &g_x[seg0 + wid][lane * 4];
    atomicAdd(dst + 0, r.x); atomicAdd(dst + 1, r.y);
    atomicAdd(dst + 2, r.z); atomicAdd(dst + 3, r.w);
}

// ---------------- stage 4: silu(x) @ W2 + b2f -> out ----------------------
// 64 blocks x 256 threads; warp per segment (8 segs/block x 64 = 512).
__global__ void out_kernel(const float* __restrict__ W2,
                           const float* __restrict__ b2f,
                           float* __restrict__ out) {
    int tid  = threadIdx.x;
    int wid  = tid >> 5;
    int lane = tid & 31;
    int seg  = blockIdx.x * 8 + wid;

    float4 x = *reinterpret_cast<const float4*>(&g_x[seg][lane * 4]);
    x.x = x.x / (1.f + __expf(-x.x));
    x.y = x.y / (1.f + __expf(-x.y));
    x.z = x.z / (1.f + __expf(-x.z));
    x.w = x.w / (1.f + __expf(-x.w));
    float4 w = reinterpret_cast<const float4*>(W2)[lane];
    float p = x.x * w.x + x.y * w.y + x.z * w.z + x.w * w.w;
    #pragma unroll
    for (int o = 16; o; o >>= 1) p += __shfl_xor_sync(0xffffffffu, p, o);
    if (lane == 0) out[seg] = p + b2f[0];
}

// ---------------- launch ----------------
extern "C" void kernel_launch(void* const* d_in, const int* in_sizes, int n_in,
                              void* d_out, int out_size) {
    const float* h0  = (const float*)d_in[0];
    const float* h1  = (const float*)d_in[1];
    const float* h2  = (const float*)d_in[2];
    const int*   b0  = (const int*)d_in[3];
    const int*   b1  = (const int*)d_in[4];
    const int*   b2  = (const int*)d_in[5];
    const float* Wg0 = (const float*)d_in[6];
    const float* bg0 = (const float*)d_in[7];
    const float* Wg1 = (const float*)d_in[8];
    const float* bg1 = (const float*)d_in[9];
    const float* Wg2 = (const float*)d_in[10];
    const float* bg2 = (const float*)d_in[11];
    const float* Wp0 = (const float*)d_in[12];
    const float* bp0 = (const float*)d_in[13];
    const float* Wp1 = (const float*)d_in[14];
    const float* bp1 = (const float*)d_in[15];
    const float* Wp2 = (const float*)d_in[16];
    const float* bp2 = (const float*)d_in[17];
    const float* gamma = (const float*)d_in[18];
    const float* beta  = (const float*)d_in[19];
    const float* W1  = (const float*)d_in[20];
    const float* b1f = (const float*)d_in[21];
    const float* W2  = (const float*)d_in[22];
    const float* b2f = (const float*)d_in[23];

    int N0 = in_sizes[3];
    int N1 = in_sizes[4];
    int N2 = in_sizes[5];

    init_kernel<<<512, 256>>>(bp0, bp1, bp2, b1f);

    dim3 gpool(POOL_BLOCKS_X, RANKS);
    pool_kernel<<<gpool, POOL_THREADS>>>(h0, h1, h2, b0, b1, b2,
                                         Wg0, Wg1, Wg2, bg0, bg1, bg2,
                                         N0, N1, N2);

    dim3 gp(B / 16, 4, RANKS);
    proj_kernel<<<gp, 256>>>(Wp0, Wp1, Wp2);

    dim3 gf(B / 8, 3);
    final_kernel<<<gf, 256>>>(gamma, beta, W1);

    out_kernel<<<B / 8, 256>>>(W2, b2f, (float*)d_out);
}